// round 2
// baseline (speedup 1.0000x reference)
#include <cuda_runtime.h>
#include <cstdint>

typedef unsigned long long ull;

#define HD 128
#define DD 256

// ---------- packed f32x2 helpers (Blackwell sm_100+) ----------
__device__ __forceinline__ void fma2(ull &d, ull a, ull b) {
    asm("fma.rn.f32x2 %0, %1, %2, %0;" : "+l"(d) : "l"(a), "l"(b));
}
__device__ __forceinline__ ull add2(ull a, ull b) {
    ull d; asm("add.rn.f32x2 %0, %1, %2;" : "=l"(d) : "l"(a), "l"(b)); return d;
}
__device__ __forceinline__ float2 unpack2(ull u) {
    float2 r; asm("mov.b64 {%0, %1}, %2;" : "=f"(r.x), "=f"(r.y) : "l"(u)); return r;
}

// ---------- Kernel 1: xW = input @ Wi^T + bi, written into out[S,128] ----------
// block = 128 threads (one per h), 32 s-rows per block.
__global__ void __launch_bounds__(128) gemm_xw_kernel(
    const float* __restrict__ X,   // [S, 256]
    const float* __restrict__ Wi,  // [128, 256]
    const float* __restrict__ bi,  // [128]
    float* __restrict__ out, int S)
{
    __shared__ __align__(16) float xs[32][DD];
    const int h  = threadIdx.x;
    const int s0 = blockIdx.x * 32;

    // load input tile: 32*256 floats = 2048 float4, 16 per thread, coalesced
    const float4* Xg  = (const float4*)(X + (size_t)s0 * DD);
    float4*       xs4 = (float4*)&xs[0][0];
#pragma unroll
    for (int i = 0; i < 16; i++) xs4[h + 128 * i] = Xg[h + 128 * i];
    __syncthreads();

    float acc[32];
#pragma unroll
    for (int s = 0; s < 32; s++) acc[s] = 0.f;

    const float4* wr = (const float4*)(Wi + h * DD);
#pragma unroll 4
    for (int kk = 0; kk < DD / 4; kk++) {
        float4 wv = wr[kk];
#pragma unroll
        for (int s = 0; s < 32; s++) {
            float4 xv = *(const float4*)&xs[s][kk * 4];
            acc[s] = fmaf(wv.x, xv.x, acc[s]);
            acc[s] = fmaf(wv.y, xv.y, acc[s]);
            acc[s] = fmaf(wv.z, xv.z, acc[s]);
            acc[s] = fmaf(wv.w, xv.w, acc[s]);
        }
    }
    const float b = bi[h];
#pragma unroll
    for (int s = 0; s < 32; s++) out[(size_t)(s0 + s) * HD + h] = acc[s] + b;
}

// ---------- Kernel 2: sequential recurrence ----------
// 256 threads: lanes (2u, 2u+1) of warp w own output j = w*16+u; each lane
// covers 64 of the 128 K-values (32 packed f32x2 weights in registers).
// h double-buffered in shared -> one __syncthreads per step.
// xw rows prefetched 4-8 steps ahead from `out` (L2-resident), h overwrites
// the consumed xw row in-place.
__global__ void __launch_bounds__(256, 1) rnn_seq_kernel(
    const float* __restrict__ Wh,  // [128, 128]
    const float* __restrict__ bh,  // [128]
    const float* __restrict__ h0,  // [1, 128]
    float* out,                    // [S, 128]: xw in, h out
    float* hn, int S, int has_hn)
{
    __shared__ __align__(16) float sh[2][HD];
    const int tid  = threadIdx.x;
    const int lane = tid & 31;
    const int wrp  = tid >> 5;
    const int half = lane & 1;
    const int j    = wrp * 16 + (lane >> 1);

    // Wh row j, half-K segment, packed as 32 f32x2 in registers
    ull w[32];
    {
        const ulonglong2* wp = (const ulonglong2*)(Wh + j * HD + half * 64);
#pragma unroll
        for (int i = 0; i < 16; i++) { ulonglong2 v = wp[i]; w[2*i] = v.x; w[2*i+1] = v.y; }
    }
    const float bj = bh[j];

    if (tid < HD) sh[0][tid] = h0[tid];

    float xw[4], xwn[4];
#pragma unroll
    for (int q = 0; q < 4; q++) xw[q] = out[q * HD + j];

    __syncthreads();

    for (int t = 0; t < S; t += 4) {
        // prefetch the next 4 xw rows (consumed next iteration)
#pragma unroll
        for (int q = 0; q < 4; q++) {
            int tn = t + 4 + q;
            xwn[q] = (tn < S) ? out[(size_t)tn * HD + j] : 0.f;
        }
#pragma unroll
        for (int q = 0; q < 4; q++) {
            const ulonglong2* hp = (const ulonglong2*)(&sh[q & 1][half * 64]);
            ull a0 = 0, a1 = 0, a2 = 0, a3 = 0;
#pragma unroll
            for (int i = 0; i < 16; i += 2) {
                ulonglong2 hv0 = hp[i];
                ulonglong2 hv1 = hp[i + 1];
                fma2(a0, w[2*i    ], hv0.x);
                fma2(a1, w[2*i + 1], hv0.y);
                fma2(a2, w[2*i + 2], hv1.x);
                fma2(a3, w[2*i + 3], hv1.y);
            }
            float2 r = unpack2(add2(add2(a0, a1), add2(a2, a3)));
            float part = r.x + r.y;
            part += __shfl_xor_sync(0xFFFFFFFFu, part, 1);
            float z = xw[q] + bj + part;
            // tanh(z) = 1 - 2/(exp(2z)+1); exact at +-inf overflow, rel err ~1e-6
            float e = __expf(2.0f * z);
            float hval = 1.0f - __fdividef(2.0f, e + 1.0f);
            if (half == 0) sh[(q & 1) ^ 1][j] = hval;            // publish h_t
            else           out[(size_t)(t + q) * HD + j] = hval; // stream to gmem
            __syncthreads();
        }
#pragma unroll
        for (int q = 0; q < 4; q++) xw[q] = xwn[q];
    }

    if (has_hn && tid < HD) hn[tid] = sh[((S - 1) & 1) ^ 1][tid];
}

// ---------- launcher ----------
extern "C" void kernel_launch(void* const* d_in, const int* in_sizes, int n_in,
                              void* d_out, int out_size)
{
    (void)n_in;
    const float* input = (const float*)d_in[0];  // [S, 256]
    const float* h0    = (const float*)d_in[1];  // [1, 128]
    const float* Wi    = (const float*)d_in[2];  // [128, 256]
    const float* bi    = (const float*)d_in[3];  // [128]
    const float* Wh    = (const float*)d_in[4];  // [128, 128]
    const float* bh    = (const float*)d_in[5];  // [128]
    float* out = (float*)d_out;

    const int S = in_sizes[0] / DD;
    const int has_hn = (out_size >= S * HD + HD) ? 1 : 0;
    float* hn = out + (size_t)S * HD;

    gemm_xw_kernel<<<(S + 31) / 32, 128>>>(input, Wi, bi, out, S);
    rnn_seq_kernel<<<1, 256>>>(Wh, bh, h0, out, hn, S, has_hn);
}

// round 4
// speedup vs baseline: 1.4737x; 1.4737x over previous
#include <cuda_runtime.h>
#include <cstdint>

typedef unsigned long long ull;

#define HD 128
#define DD 256

// ---------- packed f32x2 helpers (Blackwell sm_100+) ----------
__device__ __forceinline__ void fma2(ull &d, ull a, ull b) {
    asm("fma.rn.f32x2 %0, %1, %2, %0;" : "+l"(d) : "l"(a), "l"(b));
}
__device__ __forceinline__ ull add2(ull a, ull b) {
    ull d; asm("add.rn.f32x2 %0, %1, %2;" : "=l"(d) : "l"(a), "l"(b)); return d;
}
__device__ __forceinline__ float2 unpack2(ull u) {
    float2 r; asm("mov.b64 {%0, %1}, %2;" : "=f"(r.x), "=f"(r.y) : "l"(u)); return r;
}
__device__ __forceinline__ float ex2_approx(float x) {
    float r; asm("ex2.approx.f32 %0, %1;" : "=f"(r) : "f"(x)); return r;
}
__device__ __forceinline__ float rcp_approx(float x) {
    float r; asm("rcp.approx.f32 %0, %1;" : "=f"(r) : "f"(x)); return r;
}

// ---------- Kernel 1: xW = input @ Wi^T + bi, written into out[S,128] ----------
__global__ void __launch_bounds__(128) gemm_xw_kernel(
    const float* __restrict__ X,   // [S, 256]
    const float* __restrict__ Wi,  // [128, 256]
    const float* __restrict__ bi,  // [128]
    float* __restrict__ out, int S)
{
    __shared__ __align__(16) float xs[32][DD];
    const int h  = threadIdx.x;
    const int s0 = blockIdx.x * 32;

    const float4* Xg  = (const float4*)(X + (size_t)s0 * DD);
    float4*       xs4 = (float4*)&xs[0][0];
#pragma unroll
    for (int i = 0; i < 16; i++) xs4[h + 128 * i] = Xg[h + 128 * i];
    __syncthreads();

    float acc[32];
#pragma unroll
    for (int s = 0; s < 32; s++) acc[s] = 0.f;

    const float4* wr = (const float4*)(Wi + h * DD);
#pragma unroll 4
    for (int kk = 0; kk < DD / 4; kk++) {
        float4 wv = wr[kk];
#pragma unroll
        for (int s = 0; s < 32; s++) {
            float4 xv = *(const float4*)&xs[s][kk * 4];
            acc[s] = fmaf(wv.x, xv.x, acc[s]);
            acc[s] = fmaf(wv.y, xv.y, acc[s]);
            acc[s] = fmaf(wv.z, xv.z, acc[s]);
            acc[s] = fmaf(wv.w, xv.w, acc[s]);
        }
    }
    const float b = bi[h];
#pragma unroll
    for (int s = 0; s < 32; s++) out[(size_t)(s0 + s) * HD + h] = acc[s] + b;
}

// ---------- Kernel 2: sequential recurrence ----------
// 128 threads = 4 warps, one per SMSP. Lane j owns output j and holds the
// full Wh row j in registers (64 f32x2). h double-buffered in shared; every
// h read is a broadcast LDS.128 (all lanes same address, conflict-free).
// No shfl reduce: 8 in-lane accumulators + 3-level f32x2 tree.
// One __syncthreads per step. xw rows prefetched 8 steps ahead (L2-resident),
// bias folded in off the critical path; h overwrites consumed xw rows.
__global__ void __launch_bounds__(128, 1) rnn_seq_kernel(
    const float* __restrict__ Wh,  // [128, 128]
    const float* __restrict__ bh,  // [128]
    const float* __restrict__ h0,  // [1, 128]
    float* out,                    // [S, 128]: xw in, h out
    float* hn, int S, int has_hn)
{
    __shared__ __align__(16) float sh[2][HD];
    const int j = threadIdx.x;

    // full Wh row j in registers: 64 packed f32x2
    ull w[64];
    {
        const ulonglong2* wp = (const ulonglong2*)(Wh + j * HD);
#pragma unroll
        for (int i = 0; i < 32; i++) { ulonglong2 v = wp[i]; w[2*i] = v.x; w[2*i+1] = v.y; }
    }
    const float bj = bh[j];

    sh[0][j] = h0[j];

    float xwb[8], xwn[8];
#pragma unroll
    for (int q = 0; q < 8; q++) xwb[q] = out[q * HD + j] + bj;

    __syncthreads();

    for (int t = 0; t < S; t += 8) {
        // prefetch the next 8 xw rows (consumed next outer iteration)
#pragma unroll
        for (int q = 0; q < 8; q++) {
            int tn = t + 8 + q;
            xwn[q] = (tn < S) ? out[(size_t)tn * HD + j] : 0.f;
        }
#pragma unroll
        for (int q = 0; q < 8; q++) {
            const int buf  = q & 1;        // step index t+q has parity q (t % 8 == 0)
            const int nbuf = buf ^ 1;
            const ulonglong2* hp = (const ulonglong2*)(&sh[buf][0]);

            ull a0 = 0, a1 = 0, a2 = 0, a3 = 0, a4 = 0, a5 = 0, a6 = 0, a7 = 0;
#pragma unroll
            for (int i = 0; i < 8; i++) {
                ulonglong2 hv0 = hp[4*i + 0];
                ulonglong2 hv1 = hp[4*i + 1];
                ulonglong2 hv2 = hp[4*i + 2];
                ulonglong2 hv3 = hp[4*i + 3];
                fma2(a0, w[8*i + 0], hv0.x);
                fma2(a1, w[8*i + 1], hv0.y);
                fma2(a2, w[8*i + 2], hv1.x);
                fma2(a3, w[8*i + 3], hv1.y);
                fma2(a4, w[8*i + 4], hv2.x);
                fma2(a5, w[8*i + 5], hv2.y);
                fma2(a6, w[8*i + 6], hv3.x);
                fma2(a7, w[8*i + 7], hv3.y);
            }
            // 3-level packed reduce, then horizontal add
            ull s0 = add2(a0, a1), s1 = add2(a2, a3), s2 = add2(a4, a5), s3 = add2(a6, a7);
            ull s4 = add2(s0, s1), s5 = add2(s2, s3);
            float2 rr = unpack2(add2(s4, s5));
            float z = (rr.x + rr.y) + xwb[q];

            // tanh(z) = 1 - 2/(exp(2z)+1); ex2+rcp approx, rel err ~1e-6
            float e = ex2_approx(z * 2.8853900817779268f);   // exp(2z) = 2^(z*2/ln2)
            float r = rcp_approx(e + 1.0f);
            float hval = fmaf(-2.0f, r, 1.0f);

            sh[nbuf][j] = hval;                        // publish h_t
            out[(size_t)(t + q) * HD + j] = hval;      // coalesced stream to gmem
            __syncthreads();
        }
#pragma unroll
        for (int q = 0; q < 8; q++) xwb[q] = xwn[q] + bj;
    }

    if (has_hn) hn[j] = sh[S & 1][j];
}

// ---------- launcher ----------
extern "C" void kernel_launch(void* const* d_in, const int* in_sizes, int n_in,
                              void* d_out, int out_size)
{
    (void)n_in;
    const float* input = (const float*)d_in[0];  // [S, 256]
    const float* h0    = (const float*)d_in[1];  // [1, 128]
    const float* Wi    = (const float*)d_in[2];  // [128, 256]
    const float* bi    = (const float*)d_in[3];  // [128]
    const float* Wh    = (const float*)d_in[4];  // [128, 128]
    const float* bh    = (const float*)d_in[5];  // [128]
    float* out = (float*)d_out;

    const int S = in_sizes[0] / DD;
    const int has_hn = (out_size >= S * HD + HD) ? 1 : 0;
    float* hn = out + (size_t)S * HD;

    gemm_xw_kernel<<<(S + 31) / 32, 128>>>(input, Wi, bi, out, S);
    rnn_seq_kernel<<<1, 128>>>(Wh, bh, h0, out, hn, S, has_hn);
}